// round 5
// baseline (speedup 1.0000x reference)
#include <cuda_runtime.h>
#include <cuda_bf16.h>
#include <math.h>
#include <stdint.h>

#define HID   1024
#define BATCH 32
#define SEQ   512
#define RIMG  196
#define NCT   8
#define MT    128
#define NT    128
#define KC    32
#define NCHUNK (HID / KC)
#define ROWB  80                      // smem row: 64B data + 16B pad
#define VERB  (128 * ROWB)            // 10240 B per matrix version
#define STAGEB (4 * VERB)             // Ahi, Alo, Bhi, Blo = 40960
#define NSTAGE 3
#define WV_OFF  (NSTAGE * STAGEB)     // 122880
#define RED_OFF (WV_OFF + 512)
#define SMEM_DYN (RED_OFF + 1024)

// ---------------- scratch ----------------
__device__ float g_part1[NCT * BATCH * RIMG];
__device__ float g_part2[NCT * BATCH * SEQ];
__device__ float g_w1[BATCH * RIMG];
__device__ float g_w2[BATCH * SEQ];
__device__ float g_v[BATCH * HID];
__device__ float g_u[BATCH * HID];

// pre-split bf16 hi/lo copies
__device__ __nv_bfloat16 g_dns_hi[BATCH * SEQ * HID];
__device__ __nv_bfloat16 g_dns_lo[BATCH * SEQ * HID];
__device__ __nv_bfloat16 g_img_hi[BATCH * RIMG * HID];
__device__ __nv_bfloat16 g_img_lo[BATCH * RIMG * HID];
__device__ __nv_bfloat16 g_wi_hi[HID * HID];
__device__ __nv_bfloat16 g_wi_lo[HID * HID];
__device__ __nv_bfloat16 g_wd_hi[HID * HID];
__device__ __nv_bfloat16 g_wd_lo[HID * HID];

// ---------------- helpers ----------------
__device__ __forceinline__ uint32_t smem_u32(const void* p) {
    uint32_t a;
    asm("{ .reg .u64 t; cvta.to.shared.u64 t, %1; cvt.u32.u64 %0, t; }" : "=r"(a) : "l"(p));
    return a;
}
__device__ __forceinline__ void ldsm4(uint32_t* r, uint32_t addr) {
    asm volatile("ldmatrix.sync.aligned.m8n8.x4.shared.b16 {%0,%1,%2,%3}, [%4];"
                 : "=r"(r[0]), "=r"(r[1]), "=r"(r[2]), "=r"(r[3]) : "r"(addr));
}
__device__ __forceinline__ void mma16816(float* c, const uint32_t* a,
                                         uint32_t b0, uint32_t b1) {
    asm volatile(
        "mma.sync.aligned.m16n8k16.row.col.f32.bf16.bf16.f32 "
        "{%0,%1,%2,%3}, {%4,%5,%6,%7}, {%8,%9}, {%0,%1,%2,%3};"
        : "+f"(c[0]), "+f"(c[1]), "+f"(c[2]), "+f"(c[3])
        : "r"(a[0]), "r"(a[1]), "r"(a[2]), "r"(a[3]), "r"(b0), "r"(b1));
}
#define CP16(s, g) \
    asm volatile("cp.async.cg.shared.global [%0], [%1], 16;" :: "r"(s), "l"(g) : "memory")
#define CP_COMMIT() asm volatile("cp.async.commit_group;" ::: "memory")

__device__ __forceinline__ void split8(float4 va, float4 vb, uint4& hi, uint4& lo) {
    float f[8] = {va.x, va.y, va.z, va.w, vb.x, vb.y, vb.z, vb.w};
    uint32_t h[4], l[4];
#pragma unroll
    for (int i = 0; i < 4; i++) {
        __nv_bfloat16 h0 = __float2bfloat16_rn(f[2 * i]);
        __nv_bfloat16 h1 = __float2bfloat16_rn(f[2 * i + 1]);
        __nv_bfloat16 l0 = __float2bfloat16_rn(f[2 * i] - __bfloat162float(h0));
        __nv_bfloat16 l1 = __float2bfloat16_rn(f[2 * i + 1] - __bfloat162float(h1));
        __nv_bfloat162 hp; hp.x = h0; hp.y = h1;
        __nv_bfloat162 lp; lp.x = l0; lp.y = l1;
        h[i] = *reinterpret_cast<uint32_t*>(&hp);
        l[i] = *reinterpret_cast<uint32_t*>(&lp);
    }
    hi.x = h[0]; hi.y = h[1]; hi.z = h[2]; hi.w = h[3];
    lo.x = l[0]; lo.y = l[1]; lo.z = l[2]; lo.w = l[3];
}
__device__ __forceinline__ float fast_tanh(float x) {
    return 1.f - 2.f / (__expf(2.f * x) + 1.f);
}

// ---------------------------------------------------------------------------
// elementwise fp32 -> bf16 hi/lo split (8 floats per thread)
// ---------------------------------------------------------------------------
__global__ __launch_bounds__(256)
void presplit(const float* __restrict__ in, __nv_bfloat16* __restrict__ hi,
              __nv_bfloat16* __restrict__ lo)
{
    const int i = blockIdx.x * blockDim.x + threadIdx.x;
    const float4* p = (const float4*)in + (size_t)i * 2;
    float4 a = p[0], b = p[1];
    uint4 h, l;
    split8(a, b, h, l);
    ((uint4*)hi)[i] = h;
    ((uint4*)lo)[i] = l;
}

// ---------------------------------------------------------------------------
// pre-split bf16 3-product mma.sync GEMM(X·Wᵀ) + tanh + dot(wvec), cp.async
// 3-stage pipeline. part[ntile*Ntot + m] = partial over this 128-col tile.
// ---------------------------------------------------------------------------
__global__ __launch_bounds__(256, 1)
void gemm_mma(const __nv_bfloat16* __restrict__ Xhi, const __nv_bfloat16* __restrict__ Xlo,
              const __nv_bfloat16* __restrict__ Whi, const __nv_bfloat16* __restrict__ Wlo,
              const float* __restrict__ wvec, float* __restrict__ part, int Ntot)
{
    extern __shared__ char smem[];
    const uint32_t sb = smem_u32(smem);
    const int tid = threadIdx.x, lane = tid & 31, wid = tid >> 5;
    const int ntile = blockIdx.x, mtile = blockIdx.y;

    float* wvsh = (float*)(smem + WV_OFF);
    float* red  = (float*)(smem + RED_OFF);
    if (tid < 128) wvsh[tid] = wvec[ntile * NT + tid];

    const int row  = tid >> 1;
    const int half = tid & 1;
    const size_t aRow = (size_t)(mtile * MT + row) * HID;
    const size_t bRow = (size_t)(ntile * NT + row) * HID;
    const char* pAh = (const char*)(Xhi + aRow) + half * 32;
    const char* pAl = (const char*)(Xlo + aRow) + half * 32;
    const char* pBh = (const char*)(Whi + bRow) + half * 32;
    const char* pBl = (const char*)(Wlo + bRow) + half * 32;
    const uint32_t st = (uint32_t)(row * ROWB + half * 32);

    const int m_off = (wid & 3) * 32;
    const int n_off = (wid >> 2) * 64;
    const int lm_row  = lane & 15;
    const int lm_colb = (lane & 16) ? 16 : 0;

    float acc[2][8][4];
#pragma unroll
    for (int t = 0; t < 2; t++)
#pragma unroll
        for (int n = 0; n < 8; n++)
#pragma unroll
            for (int j = 0; j < 4; j++) acc[t][n][j] = 0.f;

#define ISSUE(ci)                                                       \
    do {                                                                \
        const uint32_t s0 = sb + ((ci) % NSTAGE) * STAGEB + st;         \
        const size_t  go = (size_t)(ci) * 64;                           \
        CP16(s0,                 pAh + go);                             \
        CP16(s0 + 16,            pAh + go + 16);                        \
        CP16(s0 + VERB,          pAl + go);                             \
        CP16(s0 + VERB + 16,     pAl + go + 16);                        \
        CP16(s0 + 2 * VERB,      pBh + go);                             \
        CP16(s0 + 2 * VERB + 16, pBh + go + 16);                        \
        CP16(s0 + 3 * VERB,      pBl + go);                             \
        CP16(s0 + 3 * VERB + 16, pBl + go + 16);                        \
        CP_COMMIT();                                                    \
    } while (0)

    ISSUE(0);
    ISSUE(1);

    for (int i = 0; i < NCHUNK; ++i) {
        if (i < NCHUNK - 1)
            asm volatile("cp.async.wait_group 1;" ::: "memory");
        else
            asm volatile("cp.async.wait_group 0;" ::: "memory");
        __syncthreads();
        if (i + 2 < NCHUNK) ISSUE(i + 2);

        const uint32_t SA = sb + (i % NSTAGE) * STAGEB;
        const uint32_t SB = SA + 2 * VERB;
#pragma unroll
        for (int ks = 0; ks < 2; ks++) {
            uint32_t ah[2][4], al[2][4];
#pragma unroll
            for (int t = 0; t < 2; t++) {
                uint32_t ad = SA + (uint32_t)((m_off + t * 16 + lm_row) * ROWB + ks * 32 + lm_colb);
                ldsm4(ah[t], ad);
                ldsm4(al[t], ad + VERB);
            }
            uint32_t bh[4][4], bl[4][4];
#pragma unroll
            for (int q = 0; q < 4; q++) {
                uint32_t bd = SB + (uint32_t)((n_off + q * 16 + lm_row) * ROWB + ks * 32 + lm_colb);
                ldsm4(bh[q], bd);
                ldsm4(bl[q], bd + VERB);
            }
#pragma unroll
            for (int t = 0; t < 2; t++)
#pragma unroll
                for (int n8 = 0; n8 < 8; n8++) {
                    const int q = n8 >> 1, u = n8 & 1;
                    mma16816(acc[t][n8], ah[t], bh[q][u], bh[q][u + 2]);
                    mma16816(acc[t][n8], ah[t], bl[q][u], bl[q][u + 2]);
                    mma16816(acc[t][n8], al[t], bh[q][u], bh[q][u + 2]);
                }
        }
    }

    // epilogue: tanh + dot(wv) -> per-row partials
    float s0[2] = {0.f, 0.f}, s1[2] = {0.f, 0.f};
#pragma unroll
    for (int t = 0; t < 2; t++)
#pragma unroll
        for (int n8 = 0; n8 < 8; n8++) {
            const float w0 = wvsh[n_off + n8 * 8 + (lane & 3) * 2];
            const float w1 = wvsh[n_off + n8 * 8 + (lane & 3) * 2 + 1];
            s0[t] = fmaf(fast_tanh(acc[t][n8][0]), w0, s0[t]);
            s0[t] = fmaf(fast_tanh(acc[t][n8][1]), w1, s0[t]);
            s1[t] = fmaf(fast_tanh(acc[t][n8][2]), w0, s1[t]);
            s1[t] = fmaf(fast_tanh(acc[t][n8][3]), w1, s1[t]);
        }
#pragma unroll
    for (int o = 1; o <= 2; o <<= 1) {
#pragma unroll
        for (int t = 0; t < 2; t++) {
            s0[t] += __shfl_xor_sync(0xffffffffu, s0[t], o);
            s1[t] += __shfl_xor_sync(0xffffffffu, s1[t], o);
        }
    }
    __syncthreads();
    if ((lane & 3) == 0) {
        const int r = lane >> 2;
        float* rw = red + (wid >> 2) * 128;
        rw[m_off + r]          = s0[0];
        rw[m_off + r + 8]      = s1[0];
        rw[m_off + 16 + r]     = s0[1];
        rw[m_off + 16 + r + 8] = s1[1];
    }
    __syncthreads();
    if (tid < 128)
        part[ntile * Ntot + mtile * MT + tid] = red[tid] + red[128 + tid];
}

// ---------------------------------------------------------------------------
__device__ __forceinline__ float warpRedMax(float v) {
#pragma unroll
    for (int o = 16; o > 0; o >>= 1) v = fmaxf(v, __shfl_xor_sync(0xffffffffu, v, o));
    return v;
}
__device__ __forceinline__ float warpRedSum(float v) {
#pragma unroll
    for (int o = 16; o > 0; o >>= 1) v += __shfl_xor_sync(0xffffffffu, v, o);
    return v;
}

__global__ void softmax_rows(const float* __restrict__ part, int N, int n,
                             float* __restrict__ w)
{
    __shared__ float sh[8];
    const int b = blockIdx.x, tid = threadIdx.x, base = b * n;

    float m = -1e30f;
    for (int i = tid; i < n; i += 256) {
        float x = 0.f;
#pragma unroll
        for (int c = 0; c < NCT; c++) x += part[c * N + base + i];
        w[base + i] = x;
        m = fmaxf(m, x);
    }
    m = warpRedMax(m);
    if ((tid & 31) == 0) sh[tid >> 5] = m;
    __syncthreads();
    float M = sh[0];
#pragma unroll
    for (int t = 1; t < 8; t++) M = fmaxf(M, sh[t]);

    float sum = 0.f;
    for (int i = tid; i < n; i += 256) {
        float e = expf(w[base + i] - M);
        w[base + i] = e;
        sum += e;
    }
    sum = warpRedSum(sum);
    __syncthreads();
    if ((tid & 31) == 0) sh[tid >> 5] = sum;
    __syncthreads();
    float S = 0.f;
#pragma unroll
    for (int t = 0; t < 8; t++) S += sh[t];
    const float inv = 1.f / S;
    for (int i = tid; i < n; i += 256) w[base + i] *= inv;
}

__global__ void wsum_kernel(const float* __restrict__ w, const float* __restrict__ X,
                            int n, float* __restrict__ out)
{
    const int b = blockIdx.x;
    const int h = blockIdx.y * blockDim.x + threadIdx.x;
    const float* xb = X + (size_t)b * n * HID + h;
    const float* wb = w + b * n;
    float acc = 0.f;
#pragma unroll 4
    for (int r = 0; r < n; r++)
        acc = fmaf(__ldg(&wb[r]), xb[(size_t)r * HID], acc);
    out[b * HID + h] = acc;
}

__global__ void broadcast_kernel(const float* __restrict__ u, const float* __restrict__ v,
                                 float4* __restrict__ out)
{
    const int i  = blockIdx.x * blockDim.x + threadIdx.x;
    const int b  = i >> 17;
    const int h4 = i & 255;
    const float4* u4 = (const float4*)u;
    const float4* v4 = (const float4*)v;
    out[i] = u4[b * 256 + h4];
    out[(BATCH * SEQ * HID / 4) + i] = v4[b * 256 + h4];
}

// ---------------------------------------------------------------------------
extern "C" void kernel_launch(void* const* d_in, const int* in_sizes, int n_in,
                              void* d_out, int out_size)
{
    const float* dns    = (const float*)d_in[0];
    const float* img    = (const float*)d_in[1];
    const float* W_i1   = (const float*)d_in[4];
    const float* w_att1 = (const float*)d_in[5];
    const float* W_d2   = (const float*)d_in[7];
    const float* w_att2 = (const float*)d_in[10];
    float* out = (float*)d_out;

    float *part1, *part2, *w1, *w2, *v, *u;
    cudaGetSymbolAddress((void**)&part1, g_part1);
    cudaGetSymbolAddress((void**)&part2, g_part2);
    cudaGetSymbolAddress((void**)&w1, g_w1);
    cudaGetSymbolAddress((void**)&w2, g_w2);
    cudaGetSymbolAddress((void**)&v, g_v);
    cudaGetSymbolAddress((void**)&u, g_u);

    __nv_bfloat16 *dns_hi, *dns_lo, *img_hi, *img_lo, *wi_hi, *wi_lo, *wd_hi, *wd_lo;
    cudaGetSymbolAddress((void**)&dns_hi, g_dns_hi);
    cudaGetSymbolAddress((void**)&dns_lo, g_dns_lo);
    cudaGetSymbolAddress((void**)&img_hi, g_img_hi);
    cudaGetSymbolAddress((void**)&img_lo, g_img_lo);
    cudaGetSymbolAddress((void**)&wi_hi, g_wi_hi);
    cudaGetSymbolAddress((void**)&wi_lo, g_wi_lo);
    cudaGetSymbolAddress((void**)&wd_hi, g_wd_hi);
    cudaGetSymbolAddress((void**)&wd_lo, g_wd_lo);

    cudaFuncSetAttribute(gemm_mma, cudaFuncAttributeMaxDynamicSharedMemorySize, SMEM_DYN);

    presplit<<<(BATCH * SEQ * HID / 8) / 256, 256>>>(dns, dns_hi, dns_lo);
    presplit<<<(BATCH * RIMG * HID / 8) / 256, 256>>>(img, img_hi, img_lo);
    presplit<<<(HID * HID / 8) / 256, 256>>>(W_i1, wi_hi, wi_lo);
    presplit<<<(HID * HID / 8) / 256, 256>>>(W_d2, wd_hi, wd_lo);

    gemm_mma<<<dim3(NCT, BATCH * RIMG / MT), 256, SMEM_DYN>>>(
        img_hi, img_lo, wi_hi, wi_lo, w_att1 + HID, part1, BATCH * RIMG);
    gemm_mma<<<dim3(NCT, BATCH * SEQ / MT), 256, SMEM_DYN>>>(
        dns_hi, dns_lo, wd_hi, wd_lo, w_att2 + HID, part2, BATCH * SEQ);

    softmax_rows<<<BATCH, 256>>>(part1, BATCH * RIMG, RIMG, w1);
    softmax_rows<<<BATCH, 256>>>(part2, BATCH * SEQ, SEQ, w2);

    wsum_kernel<<<dim3(BATCH, HID / 256), 256>>>(w1, img, RIMG, v);
    wsum_kernel<<<dim3(BATCH, HID / 256), 256>>>(w2, dns, SEQ, u);

    broadcast_kernel<<<(BATCH * SEQ * HID / 4) / 256, 256>>>(u, v, (float4*)out);
}

// round 6
// speedup vs baseline: 1.1142x; 1.1142x over previous
#include <cuda_runtime.h>
#include <cuda_bf16.h>
#include <math.h>
#include <stdint.h>

#define HID   1024
#define BATCH 32
#define SEQ   512
#define RIMG  196
#define NCT   8
#define MT    128
#define NT    128
#define KC    32
#define NCHUNK (HID / KC)
#define ROWB  80                      // smem row: 64B data + 16B pad
#define VERB  (128 * ROWB)            // 10240 B per matrix version
#define STAGEB (4 * VERB)             // Ahi, Alo, Bhi, Blo = 40960
#define NSTAGE 2
#define WV_OFF  (NSTAGE * STAGEB)     // 81920
#define RED_OFF (WV_OFF + 512)
#define SMEM_DYN (RED_OFF + 1024)     // ~83.5 KB -> 2 CTAs/SM

// ---------------- scratch ----------------
__device__ float g_part1[NCT * BATCH * RIMG];
__device__ float g_part2[NCT * BATCH * SEQ];
__device__ float g_w1[BATCH * RIMG];
__device__ float g_w2[BATCH * SEQ];
__device__ float g_v[BATCH * HID];
__device__ float g_u[BATCH * HID];

__device__ __nv_bfloat16 g_dns_hi[BATCH * SEQ * HID];
__device__ __nv_bfloat16 g_dns_lo[BATCH * SEQ * HID];
__device__ __nv_bfloat16 g_img_hi[BATCH * RIMG * HID];
__device__ __nv_bfloat16 g_img_lo[BATCH * RIMG * HID];
__device__ __nv_bfloat16 g_wi_hi[HID * HID];
__device__ __nv_bfloat16 g_wi_lo[HID * HID];
__device__ __nv_bfloat16 g_wd_hi[HID * HID];
__device__ __nv_bfloat16 g_wd_lo[HID * HID];

// ---------------- helpers ----------------
__device__ __forceinline__ uint32_t smem_u32(const void* p) {
    uint32_t a;
    asm("{ .reg .u64 t; cvta.to.shared.u64 t, %1; cvt.u32.u64 %0, t; }" : "=r"(a) : "l"(p));
    return a;
}
__device__ __forceinline__ void ldsm4(uint32_t* r, uint32_t addr) {
    asm volatile("ldmatrix.sync.aligned.m8n8.x4.shared.b16 {%0,%1,%2,%3}, [%4];"
                 : "=r"(r[0]), "=r"(r[1]), "=r"(r[2]), "=r"(r[3]) : "r"(addr));
}
__device__ __forceinline__ void mma16816(float* c, const uint32_t* a,
                                         uint32_t b0, uint32_t b1) {
    asm volatile(
        "mma.sync.aligned.m16n8k16.row.col.f32.bf16.bf16.f32 "
        "{%0,%1,%2,%3}, {%4,%5,%6,%7}, {%8,%9}, {%0,%1,%2,%3};"
        : "+f"(c[0]), "+f"(c[1]), "+f"(c[2]), "+f"(c[3])
        : "r"(a[0]), "r"(a[1]), "r"(a[2]), "r"(a[3]), "r"(b0), "r"(b1));
}
#define CP16(s, g) \
    asm volatile("cp.async.cg.shared.global [%0], [%1], 16;" :: "r"(s), "l"(g) : "memory")
#define CP_COMMIT() asm volatile("cp.async.commit_group;" ::: "memory")

__device__ __forceinline__ void split8(float4 va, float4 vb, uint4& hi, uint4& lo) {
    float f[8] = {va.x, va.y, va.z, va.w, vb.x, vb.y, vb.z, vb.w};
    uint32_t h[4], l[4];
#pragma unroll
    for (int i = 0; i < 4; i++) {
        __nv_bfloat16 h0 = __float2bfloat16_rn(f[2 * i]);
        __nv_bfloat16 h1 = __float2bfloat16_rn(f[2 * i + 1]);
        __nv_bfloat16 l0 = __float2bfloat16_rn(f[2 * i] - __bfloat162float(h0));
        __nv_bfloat16 l1 = __float2bfloat16_rn(f[2 * i + 1] - __bfloat162float(h1));
        __nv_bfloat162 hp; hp.x = h0; hp.y = h1;
        __nv_bfloat162 lp; lp.x = l0; lp.y = l1;
        h[i] = *reinterpret_cast<uint32_t*>(&hp);
        l[i] = *reinterpret_cast<uint32_t*>(&lp);
    }
    hi.x = h[0]; hi.y = h[1]; hi.z = h[2]; hi.w = h[3];
    lo.x = l[0]; lo.y = l[1]; lo.z = l[2]; lo.w = l[3];
}
__device__ __forceinline__ float fast_tanh(float x) {
    return 1.f - 2.f / (__expf(2.f * x) + 1.f);
}

__global__ __launch_bounds__(256)
void presplit(const float* __restrict__ in, __nv_bfloat16* __restrict__ hi,
              __nv_bfloat16* __restrict__ lo)
{
    const int i = blockIdx.x * blockDim.x + threadIdx.x;
    const float4* p = (const float4*)in + (size_t)i * 2;
    float4 a = p[0], b = p[1];
    uint4 h, l;
    split8(a, b, h, l);
    ((uint4*)hi)[i] = h;
    ((uint4*)lo)[i] = l;
}

// ---------------------------------------------------------------------------
// product-major 3-product bf16 mma GEMM + tanh + dot(wvec); occupancy 2.
// ---------------------------------------------------------------------------
__global__ __launch_bounds__(256, 2)
void gemm_mma(const __nv_bfloat16* __restrict__ Xhi, const __nv_bfloat16* __restrict__ Xlo,
              const __nv_bfloat16* __restrict__ Whi, const __nv_bfloat16* __restrict__ Wlo,
              const float* __restrict__ wvec, float* __restrict__ part, int Ntot)
{
    extern __shared__ char smem[];
    const uint32_t sb = smem_u32(smem);
    const int tid = threadIdx.x, lane = tid & 31, wid = tid >> 5;
    const int ntile = blockIdx.x, mtile = blockIdx.y;

    float* wvsh = (float*)(smem + WV_OFF);
    float* red  = (float*)(smem + RED_OFF);
    if (tid < 128) wvsh[tid] = wvec[ntile * NT + tid];

    const int row  = tid >> 1;
    const int half = tid & 1;
    const size_t aRow = (size_t)(mtile * MT + row) * HID;
    const size_t bRow = (size_t)(ntile * NT + row) * HID;
    const char* pAh = (const char*)(Xhi + aRow) + half * 32;
    const char* pAl = (const char*)(Xlo + aRow) + half * 32;
    const char* pBh = (const char*)(Whi + bRow) + half * 32;
    const char* pBl = (const char*)(Wlo + bRow) + half * 32;
    const uint32_t st = (uint32_t)(row * ROWB + half * 32);

    const int m_off = (wid & 3) * 32;
    const int n_off = (wid >> 2) * 64;
    const int lm_row  = lane & 15;
    const int lm_colb = (lane & 16) ? 16 : 0;

    float acc[2][8][4];
#pragma unroll
    for (int t = 0; t < 2; t++)
#pragma unroll
        for (int n = 0; n < 8; n++)
#pragma unroll
            for (int j = 0; j < 4; j++) acc[t][n][j] = 0.f;

#define ISSUE(ci)                                                       \
    do {                                                                \
        const uint32_t s0 = sb + ((ci) & 1) * STAGEB + st;              \
        const size_t  go = (size_t)(ci) * 64;                           \
        CP16(s0,                 pAh + go);                             \
        CP16(s0 + 16,            pAh + go + 16);                        \
        CP16(s0 + VERB,          pAl + go);                             \
        CP16(s0 + VERB + 16,     pAl + go + 16);                        \
        CP16(s0 + 2 * VERB,      pBh + go);                             \
        CP16(s0 + 2 * VERB + 16, pBh + go + 16);                        \
        CP16(s0 + 3 * VERB,      pBl + go);                             \
        CP16(s0 + 3 * VERB + 16, pBl + go + 16);                        \
        CP_COMMIT();                                                    \
    } while (0)

    ISSUE(0);

    for (int i = 0; i < NCHUNK; ++i) {
        asm volatile("cp.async.wait_group 0;" ::: "memory");
        __syncthreads();                 // all warps done with prev compute + data visible
        if (i + 1 < NCHUNK) ISSUE(i + 1);

        const uint32_t SA = sb + (i & 1) * STAGEB;
        const uint32_t SB = SA + 2 * VERB;
#pragma unroll
        for (int ks = 0; ks < 2; ks++) {
            const uint32_t aoff = (uint32_t)(ks * 32 + lm_colb);
            uint32_t af[2][4], bf[4][4];

            // ---- product 1: Ahi x Bhi ----
#pragma unroll
            for (int t = 0; t < 2; t++)
                ldsm4(af[t], SA + (uint32_t)((m_off + t * 16 + lm_row) * ROWB) + aoff);
#pragma unroll
            for (int q = 0; q < 4; q++)
                ldsm4(bf[q], SB + (uint32_t)((n_off + q * 16 + lm_row) * ROWB) + aoff);
#pragma unroll
            for (int t = 0; t < 2; t++)
#pragma unroll
                for (int n8 = 0; n8 < 8; n8++) {
                    const int q = n8 >> 1, u = n8 & 1;
                    mma16816(acc[t][n8], af[t], bf[q][u], bf[q][u + 2]);
                }

            // ---- product 2: Ahi x Blo ----
#pragma unroll
            for (int q = 0; q < 4; q++)
                ldsm4(bf[q], SB + VERB + (uint32_t)((n_off + q * 16 + lm_row) * ROWB) + aoff);
#pragma unroll
            for (int t = 0; t < 2; t++)
#pragma unroll
                for (int n8 = 0; n8 < 8; n8++) {
                    const int q = n8 >> 1, u = n8 & 1;
                    mma16816(acc[t][n8], af[t], bf[q][u], bf[q][u + 2]);
                }

            // ---- product 3: Alo x Bhi ----
#pragma unroll
            for (int t = 0; t < 2; t++)
                ldsm4(af[t], SA + VERB + (uint32_t)((m_off + t * 16 + lm_row) * ROWB) + aoff);
#pragma unroll
            for (int q = 0; q < 4; q++)
                ldsm4(bf[q], SB + (uint32_t)((n_off + q * 16 + lm_row) * ROWB) + aoff);
#pragma unroll
            for (int t = 0; t < 2; t++)
#pragma unroll
                for (int n8 = 0; n8 < 8; n8++) {
                    const int q = n8 >> 1, u = n8 & 1;
                    mma16816(acc[t][n8], af[t], bf[q][u], bf[q][u + 2]);
                }
        }
    }

    // epilogue: tanh + dot(wv) -> per-row partials
    float s0[2] = {0.f, 0.f}, s1[2] = {0.f, 0.f};
#pragma unroll
    for (int t = 0; t < 2; t++)
#pragma unroll
        for (int n8 = 0; n8 < 8; n8++) {
            const float w0 = wvsh[n_off + n8 * 8 + (lane & 3) * 2];
            const float w1 = wvsh[n_off + n8 * 8 + (lane & 3) * 2 + 1];
            s0[t] = fmaf(fast_tanh(acc[t][n8][0]), w0, s0[t]);
            s0[t] = fmaf(fast_tanh(acc[t][n8][1]), w1, s0[t]);
            s1[t] = fmaf(fast_tanh(acc[t][n8][2]), w0, s1[t]);
            s1[t] = fmaf(fast_tanh(acc[t][n8][3]), w1, s1[t]);
        }
#pragma unroll
    for (int o = 1; o <= 2; o <<= 1) {
#pragma unroll
        for (int t = 0; t < 2; t++) {
            s0[t] += __shfl_xor_sync(0xffffffffu, s0[t], o);
            s1[t] += __shfl_xor_sync(0xffffffffu, s1[t], o);
        }
    }
    __syncthreads();
    if ((lane & 3) == 0) {
        const int r = lane >> 2;
        float* rw = red + (wid >> 2) * 128;
        rw[m_off + r]          = s0[0];
        rw[m_off + r + 8]      = s1[0];
        rw[m_off + 16 + r]     = s0[1];
        rw[m_off + 16 + r + 8] = s1[1];
    }
    __syncthreads();
    if (tid < 128)
        part[ntile * Ntot + mtile * MT + tid] = red[tid] + red[128 + tid];
}

// ---------------------------------------------------------------------------
__device__ __forceinline__ float warpRedMax(float v) {
#pragma unroll
    for (int o = 16; o > 0; o >>= 1) v = fmaxf(v, __shfl_xor_sync(0xffffffffu, v, o));
    return v;
}
__device__ __forceinline__ float warpRedSum(float v) {
#pragma unroll
    for (int o = 16; o > 0; o >>= 1) v += __shfl_xor_sync(0xffffffffu, v, o);
    return v;
}

__global__ void softmax_rows(const float* __restrict__ part, int N, int n,
                             float* __restrict__ w)
{
    __shared__ float sh[8];
    const int b = blockIdx.x, tid = threadIdx.x, base = b * n;

    float m = -1e30f;
    for (int i = tid; i < n; i += 256) {
        float x = 0.f;
#pragma unroll
        for (int c = 0; c < NCT; c++) x += part[c * N + base + i];
        w[base + i] = x;
        m = fmaxf(m, x);
    }
    m = warpRedMax(m);
    if ((tid & 31) == 0) sh[tid >> 5] = m;
    __syncthreads();
    float M = sh[0];
#pragma unroll
    for (int t = 1; t < 8; t++) M = fmaxf(M, sh[t]);

    float sum = 0.f;
    for (int i = tid; i < n; i += 256) {
        float e = expf(w[base + i] - M);
        w[base + i] = e;
        sum += e;
    }
    sum = warpRedSum(sum);
    __syncthreads();
    if ((tid & 31) == 0) sh[tid >> 5] = sum;
    __syncthreads();
    float S = 0.f;
#pragma unroll
    for (int t = 0; t < 8; t++) S += sh[t];
    const float inv = 1.f / S;
    for (int i = tid; i < n; i += 256) w[base + i] *= inv;
}

__global__ void wsum_kernel(const float* __restrict__ w, const float* __restrict__ X,
                            int n, float* __restrict__ out)
{
    const int b = blockIdx.x;
    const int h = blockIdx.y * blockDim.x + threadIdx.x;
    const float* xb = X + (size_t)b * n * HID + h;
    const float* wb = w + b * n;
    float acc = 0.f;
#pragma unroll 4
    for (int r = 0; r < n; r++)
        acc = fmaf(__ldg(&wb[r]), xb[(size_t)r * HID], acc);
    out[b * HID + h] = acc;
}

__global__ void broadcast_kernel(const float* __restrict__ u, const float* __restrict__ v,
                                 float4* __restrict__ out)
{
    const int i  = blockIdx.x * blockDim.x + threadIdx.x;
    const int b  = i >> 17;
    const int h4 = i & 255;
    const float4* u4 = (const float4*)u;
    const float4* v4 = (const float4*)v;
    out[i] = u4[b * 256 + h4];
    out[(BATCH * SEQ * HID / 4) + i] = v4[b * 256 + h4];
}

// ---------------------------------------------------------------------------
extern "C" void kernel_launch(void* const* d_in, const int* in_sizes, int n_in,
                              void* d_out, int out_size)
{
    const float* dns    = (const float*)d_in[0];
    const float* img    = (const float*)d_in[1];
    const float* W_i1   = (const float*)d_in[4];
    const float* w_att1 = (const float*)d_in[5];
    const float* W_d2   = (const float*)d_in[7];
    const float* w_att2 = (const float*)d_in[10];
    float* out = (float*)d_out;

    float *part1, *part2, *w1, *w2, *v, *u;
    cudaGetSymbolAddress((void**)&part1, g_part1);
    cudaGetSymbolAddress((void**)&part2, g_part2);
    cudaGetSymbolAddress((void**)&w1, g_w1);
    cudaGetSymbolAddress((void**)&w2, g_w2);
    cudaGetSymbolAddress((void**)&v, g_v);
    cudaGetSymbolAddress((void**)&u, g_u);

    __nv_bfloat16 *dns_hi, *dns_lo, *img_hi, *img_lo, *wi_hi, *wi_lo, *wd_hi, *wd_lo;
    cudaGetSymbolAddress((void**)&dns_hi, g_dns_hi);
    cudaGetSymbolAddress((void**)&dns_lo, g_dns_lo);
    cudaGetSymbolAddress((void**)&img_hi, g_img_hi);
    cudaGetSymbolAddress((void**)&img_lo, g_img_lo);
    cudaGetSymbolAddress((void**)&wi_hi, g_wi_hi);
    cudaGetSymbolAddress((void**)&wi_lo, g_wi_lo);
    cudaGetSymbolAddress((void**)&wd_hi, g_wd_hi);
    cudaGetSymbolAddress((void**)&wd_lo, g_wd_lo);

    cudaFuncSetAttribute(gemm_mma, cudaFuncAttributeMaxDynamicSharedMemorySize, SMEM_DYN);

    presplit<<<(BATCH * SEQ * HID / 8) / 256, 256>>>(dns, dns_hi, dns_lo);
    presplit<<<(BATCH * RIMG * HID / 8) / 256, 256>>>(img, img_hi, img_lo);
    presplit<<<(HID * HID / 8) / 256, 256>>>(W_i1, wi_hi, wi_lo);
    presplit<<<(HID * HID / 8) / 256, 256>>>(W_d2, wd_hi, wd_lo);

    gemm_mma<<<dim3(NCT, BATCH * RIMG / MT), 256, SMEM_DYN>>>(
        img_hi, img_lo, wi_hi, wi_lo, w_att1 + HID, part1, BATCH * RIMG);
    gemm_mma<<<dim3(NCT, BATCH * SEQ / MT), 256, SMEM_DYN>>>(
        dns_hi, dns_lo, wd_hi, wd_lo, w_att2 + HID, part2, BATCH * SEQ);

    softmax_rows<<<BATCH, 256>>>(part1, BATCH * RIMG, RIMG, w1);
    softmax_rows<<<BATCH, 256>>>(part2, BATCH * SEQ, SEQ, w2);

    wsum_kernel<<<dim3(BATCH, HID / 256), 256>>>(w1, img, RIMG, v);
    wsum_kernel<<<dim3(BATCH, HID / 256), 256>>>(w2, dns, SEQ, u);

    broadcast_kernel<<<(BATCH * SEQ * HID / 4) / 256, 256>>>(u, v, (float4*)out);
}